// round 4
// baseline (speedup 1.0000x reference)
#include <cuda_runtime.h>

// Morton (Z-order) decode: x[B, C, 65536] Morton-ordered -> out[B, C, 256, 256],
// i = odd bits, j = even bits of the Morton index.
//
// R2: 16 consecutive Morton elements (16B-aligned group) form a complete 4x4
// output block with contiguous columns. Each thread:
//   - loads 4 float4s = 64 B contiguous (4 independent LDG.128, MLP=4)
//   - register-shuffles the 2x2 sub-blocks into 4 output rows
//   - stores 4 STG.128, one per row (dj is a multiple of 4 -> aligned)
// Per-warp store footprint per STG.128: 4 rows x 128 B = 16 full 32B sectors.
// Block = 256 threads * 16 elem = 4096 elems = one 64x64 output tile.

__global__ void __launch_bounds__(256, 8)
morton_decode_kernel(const float4* __restrict__ src, float* __restrict__ dst)
{
    const unsigned tile  = blockIdx.x;      // 4096-element tile id
    const unsigned slice = tile >> 4;       // (b*C + c); 16 tiles per 65536 slice
    const unsigned t4    = tile & 15u;      // tile position within slice (Morton)

    // Deinterleave 4 tile bits: odd -> i_tile (2b), even -> j_tile (2b); scale 64
    const unsigned i_tile = ((t4 >> 1) & 1u) | ((t4 >> 2) & 2u);
    const unsigned j_tile = ( t4       & 1u) | ((t4 >> 1) & 2u);

    const unsigned t = threadIdx.x;         // 0..255; source offset s = t*16

    // s bits 4..11 map alternately to j bits 2..5 (even) and i bits 2..5 (odd):
    const unsigned dj = ((t & 1u)  << 2) | ((t & 4u)  << 1) | ( t & 16u)       | ((t & 64u)  >> 1);
    const unsigned di = ((t & 2u)  << 1) | ( t & 8u)        | ((t & 32u) >> 1) | ((t & 128u) >> 2);

    // 64 B contiguous load: 4 float4s = 16 Morton elements (streaming, no reuse)
    const float4* p = src + (size_t)tile * 1024u + (size_t)t * 4u;
    const float4 a0 = __ldcs(p + 0);   // rows 0,1 cols 0,1 of the 4x4 block
    const float4 a1 = __ldcs(p + 1);   // rows 0,1 cols 2,3
    const float4 a2 = __ldcs(p + 2);   // rows 2,3 cols 0,1
    const float4 a3 = __ldcs(p + 3);   // rows 2,3 cols 2,3

    const unsigned i = i_tile * 64u + di;   // output row (multiple of 4 base)
    const unsigned j = j_tile * 64u + dj;   // output col (multiple of 4)

    float4* base = reinterpret_cast<float4*>(
        dst + (size_t)slice * 65536u + (size_t)i * 256u + j);

    // 256 floats per row = 64 float4s per row
    __stcs(base,       make_float4(a0.x, a0.y, a1.x, a1.y));  // row i
    __stcs(base + 64,  make_float4(a0.z, a0.w, a1.z, a1.w));  // row i+1
    __stcs(base + 128, make_float4(a2.x, a2.y, a3.x, a3.y));  // row i+2
    __stcs(base + 192, make_float4(a2.z, a2.w, a3.z, a3.w));  // row i+3
}

extern "C" void kernel_launch(void* const* d_in, const int* in_sizes, int n_in,
                              void* d_out, int out_size)
{
    const float4* src = (const float4*)d_in[0];
    float*        dst = (float*)d_out;

    // Total elements / 4096 elements-per-tile
    const int n_tiles = in_sizes[0] >> 12;  // 33,554,432 / 4096 = 8192
    morton_decode_kernel<<<n_tiles, 256>>>(src, dst);
}